// round 1
// baseline (speedup 1.0000x reference)
#include <cuda_runtime.h>
#include <stdint.h>

#define D 128
#define NMAX 100000
#define BN_EPS 1e-5f

// ---------------- scratch (no allocations allowed) ----------------
__device__ float g_XW[(size_t)NMAX * D];   // 51.2 MB: x @ weight
__device__ float g_sum[D];
__device__ float g_sumsq[D];
__device__ int   g_ei64;                   // 1 if edge_index is int64
__device__ int   g_et64;                   // 1 if edge_type  is int64

// ---------------- prologue: detect dtypes + zero stats ----------------
__global__ void prologue_kernel(const int* ei_as_i32, const int* et_as_i32) {
    int t = threadIdx.x;
    if (t < D) { g_sum[t] = 0.0f; g_sumsq[t] = 0.0f; }
    if (t == 0) {
        // int64 little-endian values < 2^31 have zero high words at odd i32 slots
        int allz = 1;
        #pragma unroll
        for (int k = 0; k < 16; k++) if (ei_as_i32[2 * k + 1] != 0) allz = 0;
        g_ei64 = allz;
        allz = 1;
        #pragma unroll
        for (int k = 0; k < 16; k++) if (et_as_i32[2 * k + 1] != 0) allz = 0;
        g_et64 = allz;
    }
}

// ---------------- GEMM + init of accumulator ----------------
// out[i][c] = 2*alpha[SELF_REL]*XW[i][c] + bias[c]   (self edges + bias folded in)
// blockDim = 128 (one thread per output column), 8 rows per block.
__global__ __launch_bounds__(128) void gemm_init_kernel(
    const float* __restrict__ x, const float* __restrict__ W,
    const float* __restrict__ alpha, const float* __restrict__ bias,
    float* __restrict__ out, int N, int selfRel)
{
    __shared__ float Xs[8][D];
    const int c  = threadIdx.x;
    const int r0 = blockIdx.x * 8;

    #pragma unroll
    for (int m = 0; m < 8; m++) {
        int r = r0 + m;
        Xs[m][c] = (r < N) ? x[(size_t)r * D + c] : 0.0f;
    }
    __syncthreads();

    float acc[8];
    #pragma unroll
    for (int m = 0; m < 8; m++) acc[m] = 0.0f;

    #pragma unroll 4
    for (int k = 0; k < D; k++) {
        float wv = __ldg(W + k * D + c);
        #pragma unroll
        for (int m = 0; m < 8; m++) acc[m] += Xs[m][k] * wv;
    }

    const float aself2 = 2.0f * __ldg(alpha + selfRel);
    const float b      = __ldg(bias + c);
    #pragma unroll
    for (int m = 0; m < 8; m++) {
        int r = r0 + m;
        if (r < N) {
            size_t off = (size_t)r * D + c;
            g_XW[off] = acc[m];
            out[off]  = aself2 * acc[m] + b;
        }
    }
}

// ---------------- edge scatter: one warp per edge ----------------
__device__ __forceinline__ void red_add_v4(float4* p, float x, float y, float z, float w) {
    asm volatile("red.global.add.v4.f32 [%0], {%1,%2,%3,%4};"
                 :: "l"(p), "f"(x), "f"(y), "f"(z), "f"(w) : "memory");
}

__global__ __launch_bounds__(256) void edge_kernel(
    const void* __restrict__ ei_raw, const void* __restrict__ et_raw,
    const float* __restrict__ alpha, float* __restrict__ out, long E)
{
    long e = (long)blockIdx.x * (blockDim.x >> 5) + (threadIdx.x >> 5);
    if (e >= E) return;
    const int lane = threadIdx.x & 31;

    int row, col, et;
    if (g_ei64) {
        const long long* p = (const long long*)ei_raw;
        row = (int)p[e];
        col = (int)p[E + e];
    } else {
        const int* p = (const int*)ei_raw;
        row = p[e];
        col = p[E + e];
    }
    if (g_et64) et = (int)((const long long*)et_raw)[e];
    else        et = ((const int*)et_raw)[e];

    const float a = __ldg(alpha + et);

    const float4* xr = (const float4*)(g_XW + (size_t)row * D);
    const float4* xc = (const float4*)(g_XW + (size_t)col * D);
    float4 vr = xr[lane];
    float4 vc = xc[lane];

    float4* orow = (float4*)(out + (size_t)row * D) + lane;
    float4* ocol = (float4*)(out + (size_t)col * D) + lane;

    // out[row] += a * XW[col] ; out[col] += a * XW[row]
    red_add_v4(orow, a * vc.x, a * vc.y, a * vc.z, a * vc.w);
    red_add_v4(ocol, a * vr.x, a * vr.y, a * vr.z, a * vr.w);
}

// ---------------- BN column stats ----------------
#define STAT_ROWS 256
__global__ __launch_bounds__(128) void stats_kernel(const float* __restrict__ out, int N) {
    const int c  = threadIdx.x;           // one thread per column
    const int r0 = blockIdx.x * STAT_ROWS;
    float s = 0.0f, sq = 0.0f;
    #pragma unroll 4
    for (int m = 0; m < STAT_ROWS; m++) {
        int r = r0 + m;
        if (r < N) {
            float v = out[(size_t)r * D + c];
            s  += v;
            sq += v * v;
        }
    }
    atomicAdd(&g_sum[c], s);
    atomicAdd(&g_sumsq[c], sq);
}

// ---------------- normalize in place + copy r to output tail ----------------
__global__ __launch_bounds__(256) void norm_kernel(
    float* __restrict__ out, const float* __restrict__ gamma,
    const float* __restrict__ beta, const float* __restrict__ r_in,
    float* __restrict__ r_out, int N, long r_count)
{
    __shared__ float sc[D], sh[D];
    const int t = threadIdx.x;
    if (t < D) {
        float invN = 1.0f / (float)N;
        float mean = g_sum[t] * invN;
        float var  = g_sumsq[t] * invN - mean * mean;
        float s    = gamma[t] * rsqrtf(var + BN_EPS);
        sc[t] = s;
        sh[t] = beta[t] - mean * s;
    }
    __syncthreads();

    size_t total  = (size_t)N * D;
    size_t stride = (size_t)gridDim.x * blockDim.x;
    for (size_t idx = (size_t)blockIdx.x * blockDim.x + t; idx < total; idx += stride) {
        int c = (int)(idx & (D - 1));
        out[idx] = out[idx] * sc[c] + sh[c];
    }
    // pass-through of r
    for (size_t idx = (size_t)blockIdx.x * blockDim.x + t; idx < (size_t)r_count; idx += stride) {
        r_out[idx] = r_in[idx];
    }
}

// ---------------- launch ----------------
extern "C" void kernel_launch(void* const* d_in, const int* in_sizes, int n_in,
                              void* d_out, int out_size)
{
    const float* x      = (const float*)d_in[0];
    const float* r      = (const float*)d_in[1];
    const void*  ei     = d_in[2];
    const void*  etype  = d_in[3];
    const float* W      = (const float*)d_in[4];
    const float* alpha  = (const float*)d_in[5];
    const float* bias   = (const float*)d_in[6];
    const float* gamma  = (const float*)d_in[7];
    const float* beta   = (const float*)d_in[8];
    float* out = (float*)d_out;

    const int  N       = in_sizes[0] / D;          // 100000
    const long E       = (long)in_sizes[3];        // 1600000
    const int  numRel  = in_sizes[1] / D;          // 1001
    const int  selfRel = numRel - 1;               // 1000
    const long r_count = (long)in_sizes[1];        // 1001*128

    float* r_out = out + (size_t)N * D;

    prologue_kernel<<<1, 128>>>((const int*)ei, (const int*)etype);

    gemm_init_kernel<<<(N + 7) / 8, 128>>>(x, W, alpha, bias, out, N, selfRel);

    {
        int warpsPerBlock = 256 / 32;
        long blocks = (E + warpsPerBlock - 1) / warpsPerBlock;
        edge_kernel<<<(unsigned)blocks, 256>>>(ei, etype, alpha, out, E);
    }

    stats_kernel<<<(N + STAT_ROWS - 1) / STAT_ROWS, 128>>>(out, N);

    norm_kernel<<<2048, 256>>>(out, gamma, beta, r, r_out, N, r_count);
}

// round 3
// speedup vs baseline: 1.1580x; 1.1580x over previous
#include <cuda_runtime.h>
#include <stdint.h>

#define D 128
#define NMAX 100000
#define EMAX 1600000
#define BN_EPS 1e-5f
#define NBANK 16

// ---------------- scratch (no allocations allowed) ----------------
__device__ __align__(16) float g_XW[(size_t)NMAX * D];     // 51.2 MB
__device__ __align__(16) uint2 g_adj[2 * EMAX];            // 25.6 MB packed {src, alpha_bits}
__device__ int   g_deg[NMAX];
__device__ int   g_off[NMAX + 1];
__device__ int   g_cursor[NMAX];
__device__ int   g_scan[NMAX];
__device__ int   g_part[128];
__device__ float g_sumP[NBANK][D];
__device__ float g_sumsqP[NBANK][D];
__device__ int   g_ei64;
__device__ int   g_et64;

// ---------------- prologue: dtype detect + zero small state ----------------
__global__ void prologue_kernel(const int* ei_as_i32, const int* et_as_i32) {
    int t = threadIdx.x;                      // 256 threads
    for (int i = t; i < NBANK * D; i += 256) {
        ((float*)g_sumP)[i] = 0.0f;
        ((float*)g_sumsqP)[i] = 0.0f;
    }
    if (t == 0) {
        int allz = 1;
        #pragma unroll
        for (int k = 0; k < 16; k++) if (ei_as_i32[2 * k + 1] != 0) allz = 0;
        g_ei64 = allz;
        allz = 1;
        #pragma unroll
        for (int k = 0; k < 16; k++) if (et_as_i32[2 * k + 1] != 0) allz = 0;
        g_et64 = allz;
    }
}

__global__ void zero_deg_kernel(int N) {
    int i = blockIdx.x * blockDim.x + threadIdx.x;
    if (i < N) g_deg[i] = 0;
}

// ---------------- GEMM: XW = x @ W (register-tiled outer product) ----------------
// block = 256 threads as 16x16; tile = 64 rows x 128 cols; thread = 4 rows x 8 cols.
__global__ __launch_bounds__(256) void gemm_kernel(
    const float* __restrict__ x, const float* __restrict__ W, int N)
{
    __shared__ float Xs[64][D];            // 32 KB, [row][k]
    const int tid = threadIdx.x;
    const int r0b = blockIdx.x * 64;

    for (int i = tid; i < 64 * 32; i += 256) {
        int r = i >> 5, kq = i & 31;
        float4 v = make_float4(0.f, 0.f, 0.f, 0.f);
        if (r0b + r < N) v = *(const float4*)&x[(size_t)(r0b + r) * D + kq * 4];
        *(float4*)&Xs[r][kq * 4] = v;
    }
    __syncthreads();

    const int tx = tid & 15, ty = tid >> 4;
    const int r0 = ty * 4;
    const int c0 = tx * 8;

    float acc[4][8];
    #pragma unroll
    for (int i = 0; i < 4; i++)
        #pragma unroll
        for (int j = 0; j < 8; j++) acc[i][j] = 0.0f;

    #pragma unroll 4
    for (int k = 0; k < D; k++) {
        float4 w0 = __ldg((const float4*)&W[k * D + c0]);
        float4 w1 = __ldg((const float4*)&W[k * D + c0 + 4]);
        float xr[4];
        #pragma unroll
        for (int i = 0; i < 4; i++) xr[i] = Xs[r0 + i][k];
        #pragma unroll
        for (int i = 0; i < 4; i++) {
            acc[i][0] += xr[i] * w0.x; acc[i][1] += xr[i] * w0.y;
            acc[i][2] += xr[i] * w0.z; acc[i][3] += xr[i] * w0.w;
            acc[i][4] += xr[i] * w1.x; acc[i][5] += xr[i] * w1.y;
            acc[i][6] += xr[i] * w1.z; acc[i][7] += xr[i] * w1.w;
        }
    }

    #pragma unroll
    for (int i = 0; i < 4; i++) {
        int r = r0b + r0 + i;
        if (r < N) {
            float* dst = g_XW + (size_t)r * D + c0;
            *(float4*)dst       = make_float4(acc[i][0], acc[i][1], acc[i][2], acc[i][3]);
            *(float4*)(dst + 4) = make_float4(acc[i][4], acc[i][5], acc[i][6], acc[i][7]);
        }
    }
}

// ---------------- histogram of degrees (both directions) ----------------
__global__ __launch_bounds__(256) void hist_kernel(
    const void* __restrict__ ei_raw, long E)
{
    long e = (long)blockIdx.x * blockDim.x + threadIdx.x;
    if (e >= E) return;
    int row, col;
    if (g_ei64) {
        const long long* p = (const long long*)ei_raw;
        row = (int)p[e]; col = (int)p[E + e];
    } else {
        const int* p = (const int*)ei_raw;
        row = p[e]; col = p[E + e];
    }
    atomicAdd(&g_deg[row], 1);
    atomicAdd(&g_deg[col], 1);
}

// ---------------- 3-kernel exclusive scan over g_deg ----------------
__global__ __launch_bounds__(1024) void scan1_kernel(int N) {
    __shared__ int sh[1024];
    int t = threadIdx.x;
    int i = blockIdx.x * 1024 + t;
    int v = (i < N) ? g_deg[i] : 0;
    sh[t] = v;
    __syncthreads();
    #pragma unroll
    for (int off = 1; off < 1024; off <<= 1) {
        int add = (t >= off) ? sh[t - off] : 0;
        __syncthreads();
        sh[t] += add;
        __syncthreads();
    }
    if (i < N) g_scan[i] = sh[t];
    if (t == 1023 && blockIdx.x < 128) g_part[blockIdx.x] = sh[1023];
}

__global__ void scan2_kernel(int nb) {
    if (threadIdx.x == 0) {
        if (nb > 128) nb = 128;
        int acc = 0;
        for (int b = 0; b < nb; b++) { int v = g_part[b]; g_part[b] = acc; acc += v; }
    }
}

__global__ __launch_bounds__(1024) void scan3_kernel(int N) {
    int i = blockIdx.x * 1024 + threadIdx.x;
    if (i >= N) return;
    int base = g_part[blockIdx.x];
    int inc = g_scan[i];
    int excl = base + inc - g_deg[i];
    g_off[i] = excl;
    g_cursor[i] = excl;
    if (i == N - 1) g_off[N] = base + inc;
}

// ---------------- fill adjacency ----------------
__global__ __launch_bounds__(256) void fill_kernel(
    const void* __restrict__ ei_raw, const void* __restrict__ et_raw,
    const float* __restrict__ alpha, long E)
{
    long e = (long)blockIdx.x * blockDim.x + threadIdx.x;
    if (e >= E) return;
    int row, col, et;
    if (g_ei64) {
        const long long* p = (const long long*)ei_raw;
        row = (int)p[e]; col = (int)p[E + e];
    } else {
        const int* p = (const int*)ei_raw;
        row = p[e]; col = p[E + e];
    }
    if (g_et64) et = (int)((const long long*)et_raw)[e];
    else        et = ((const int*)et_raw)[e];
    unsigned a = __float_as_uint(__ldg(alpha + et));
    int p1 = atomicAdd(&g_cursor[row], 1);
    g_adj[p1] = make_uint2((unsigned)col, a);
    int p2 = atomicAdd(&g_cursor[col], 1);
    g_adj[p2] = make_uint2((unsigned)row, a);
}

// ---------------- gather: warp per node, fused bias/self/BN-stats ----------------
__global__ __launch_bounds__(256) void gather_kernel(
    const float* __restrict__ alpha, const float* __restrict__ bias,
    float* __restrict__ out, int N, int selfRel)
{
    const int lane = threadIdx.x & 31;
    const int warpG = (blockIdx.x * blockDim.x + threadIdx.x) >> 5;
    const int nWarps = (gridDim.x * blockDim.x) >> 5;
    const float4* XW4 = (const float4*)g_XW;
    const uint4*  adj4 = (const uint4*)g_adj;

    const float a2 = 2.0f * __ldg(alpha + selfRel);
    const float4 b4 = __ldg((const float4*)bias + lane);

    float s0 = 0, s1 = 0, s2 = 0, s3 = 0;
    float q0 = 0, q1 = 0, q2 = 0, q3 = 0;

    for (int i = warpG; i < N; i += nWarps) {
        int st = g_off[i], en = g_off[i + 1];
        float4 self = XW4[(size_t)i * 32 + lane];
        float4 acc = make_float4(a2 * self.x + b4.x, a2 * self.y + b4.y,
                                 a2 * self.z + b4.z, a2 * self.w + b4.w);
        int j = st;
        // align to uint4 (2-entry) granule
        if ((j & 1) && j < en) {
            uint2 e0 = g_adj[j];
            float4 v0 = XW4[(size_t)e0.x * 32 + lane];
            float a0 = __uint_as_float(e0.y);
            acc.x += a0 * v0.x; acc.y += a0 * v0.y;
            acc.z += a0 * v0.z; acc.w += a0 * v0.w;
            j++;
        }
        for (; j + 4 <= en; j += 4) {
            uint4 p0 = adj4[j >> 1];
            uint4 p1 = adj4[(j >> 1) + 1];
            float4 v0 = XW4[(size_t)p0.x * 32 + lane];
            float4 v1 = XW4[(size_t)p0.z * 32 + lane];
            float4 v2 = XW4[(size_t)p1.x * 32 + lane];
            float4 v3 = XW4[(size_t)p1.z * 32 + lane];
            float a0 = __uint_as_float(p0.y), a1 = __uint_as_float(p0.w);
            float c2 = __uint_as_float(p1.y), c3 = __uint_as_float(p1.w);
            acc.x += a0 * v0.x + a1 * v1.x + c2 * v2.x + c3 * v3.x;
            acc.y += a0 * v0.y + a1 * v1.y + c2 * v2.y + c3 * v3.y;
            acc.z += a0 * v0.z + a1 * v1.z + c2 * v2.z + c3 * v3.z;
            acc.w += a0 * v0.w + a1 * v1.w + c2 * v2.w + c3 * v3.w;
        }
        for (; j < en; j++) {
            uint2 e0 = g_adj[j];
            float4 v0 = XW4[(size_t)e0.x * 32 + lane];
            float a0 = __uint_as_float(e0.y);
            acc.x += a0 * v0.x; acc.y += a0 * v0.y;
            acc.z += a0 * v0.z; acc.w += a0 * v0.w;
        }
        ((float4*)out)[(size_t)i * 32 + lane] = acc;
        s0 += acc.x; s1 += acc.y; s2 += acc.z; s3 += acc.w;
        q0 += acc.x * acc.x; q1 += acc.y * acc.y;
        q2 += acc.z * acc.z; q3 += acc.w * acc.w;
    }

    // block-level stats reduction
    __shared__ float ssum[D], ssq[D];
    int t = threadIdx.x;
    if (t < D) { ssum[t] = 0.0f; ssq[t] = 0.0f; }
    __syncthreads();
    int c = lane * 4;
    atomicAdd(&ssum[c + 0], s0); atomicAdd(&ssum[c + 1], s1);
    atomicAdd(&ssum[c + 2], s2); atomicAdd(&ssum[c + 3], s3);
    atomicAdd(&ssq[c + 0], q0);  atomicAdd(&ssq[c + 1], q1);
    atomicAdd(&ssq[c + 2], q2);  atomicAdd(&ssq[c + 3], q3);
    __syncthreads();
    if (t < D) {
        int bank = blockIdx.x & (NBANK - 1);
        atomicAdd(&g_sumP[bank][t], ssum[t]);
        atomicAdd(&g_sumsqP[bank][t], ssq[t]);
    }
}

// ---------------- normalize + copy r ----------------
__global__ __launch_bounds__(256) void norm_kernel(
    float* __restrict__ out, const float* __restrict__ gamma,
    const float* __restrict__ beta, const float* __restrict__ r_in,
    float* __restrict__ r_out, int N, long r_count)
{
    __shared__ float sc[D], sh[D];
    const int t = threadIdx.x;
    if (t < D) {
        float s = 0.0f, q = 0.0f;
        #pragma unroll
        for (int b = 0; b < NBANK; b++) { s += g_sumP[b][t]; q += g_sumsqP[b][t]; }
        float invN = 1.0f / (float)N;
        float mean = s * invN;
        float var = q * invN - mean * mean;
        float scl = gamma[t] * rsqrtf(var + BN_EPS);
        sc[t] = scl;
        sh[t] = beta[t] - mean * scl;
    }
    __syncthreads();

    size_t total = (size_t)N * D;
    size_t stride = (size_t)gridDim.x * blockDim.x;
    for (size_t idx = (size_t)blockIdx.x * blockDim.x + t; idx < total; idx += stride) {
        int c = (int)(idx & (D - 1));
        out[idx] = out[idx] * sc[c] + sh[c];
    }
    for (size_t idx = (size_t)blockIdx.x * blockDim.x + t; idx < (size_t)r_count; idx += stride) {
        r_out[idx] = r_in[idx];
    }
}

// ---------------- launch ----------------
extern "C" void kernel_launch(void* const* d_in, const int* in_sizes, int n_in,
                              void* d_out, int out_size)
{
    const float* x     = (const float*)d_in[0];
    const float* r     = (const float*)d_in[1];
    const void*  ei    = d_in[2];
    const void*  etype = d_in[3];
    const float* W     = (const float*)d_in[4];
    const float* alpha = (const float*)d_in[5];
    const float* bias  = (const float*)d_in[6];
    const float* gamma = (const float*)d_in[7];
    const float* beta  = (const float*)d_in[8];
    float* out = (float*)d_out;

    const int  N       = in_sizes[0] / D;       // 100000
    const long E       = (long)in_sizes[3];     // 1600000
    const int  numRel  = in_sizes[1] / D;       // 1001
    const int  selfRel = numRel - 1;            // 1000
    const long r_count = (long)in_sizes[1];

    float* r_out = out + (size_t)N * D;
    const int NB = (N + 1023) / 1024;

    prologue_kernel<<<1, 256>>>((const int*)ei, (const int*)etype);
    zero_deg_kernel<<<(N + 255) / 256, 256>>>(N);

    gemm_kernel<<<(N + 63) / 64, 256>>>(x, W, N);

    hist_kernel<<<(unsigned)((E + 255) / 256), 256>>>(ei, E);
    scan1_kernel<<<NB, 1024>>>(N);
    scan2_kernel<<<1, 32>>>(NB);
    scan3_kernel<<<NB, 1024>>>(N);
    fill_kernel<<<(unsigned)((E + 255) / 256), 256>>>(ei, etype, alpha, E);

    gather_kernel<<<1024, 256>>>(alpha, bias, out, N, selfRel);

    norm_kernel<<<2048, 256>>>(out, gamma, beta, r, r_out, N, r_count);
}

// round 5
// speedup vs baseline: 1.3052x; 1.1271x over previous
#include <cuda_runtime.h>
#include <cuda_fp16.h>
#include <stdint.h>

#define D 128
#define NMAX 100000
#define EMAX 1600000
#define BN_EPS 1e-5f
#define NBANK 16

// ---------------- scratch (no allocations allowed) ----------------
__device__ __align__(16) __half g_XWh[(size_t)NMAX * D];   // 25.6 MB: x@W in fp16
__device__ __align__(16) uint2 g_adj[2 * EMAX];            // 25.6 MB {src, alpha_bits}
__device__ int   g_deg[NMAX];
__device__ int   g_off[NMAX + 1];
__device__ int   g_cursor[NMAX];
__device__ int   g_scan[NMAX];
__device__ int   g_part[128];
__device__ float g_sumP[NBANK][D];
__device__ float g_sumsqP[NBANK][D];
__device__ int   g_ei64;
__device__ int   g_et64;

// ---------------- safe bit-cast helpers (no version-specific intrinsics) ----------------
__device__ __forceinline__ __half2 u32_to_h2(unsigned u) {
    __half2 h;
    memcpy(&h, &u, 4);
    return h;
}
__device__ __forceinline__ unsigned h2_to_u32(__half2 h) {
    unsigned u;
    memcpy(&u, &h, 4);
    return u;
}

// ---------------- prologue: dtype detect + zero stats + zero deg ----------------
__global__ void prologue_kernel(const int* ei_as_i32, const int* et_as_i32, int N) {
    int i = blockIdx.x * blockDim.x + threadIdx.x;
    if (i < N) g_deg[i] = 0;
    if (blockIdx.x == 0) {
        int t = threadIdx.x;
        for (int k = t; k < NBANK * D; k += blockDim.x) {
            ((float*)g_sumP)[k] = 0.0f;
            ((float*)g_sumsqP)[k] = 0.0f;
        }
        if (t == 0) {
            int allz = 1;
            #pragma unroll
            for (int k = 0; k < 16; k++) if (ei_as_i32[2 * k + 1] != 0) allz = 0;
            g_ei64 = allz;
            allz = 1;
            #pragma unroll
            for (int k = 0; k < 16; k++) if (et_as_i32[2 * k + 1] != 0) allz = 0;
            g_et64 = allz;
        }
    }
}

// ---------------- fused GEMM (fp16 out) + degree histogram ----------------
// blocks [0, GB): GEMM tile 64 rows x 128 cols, thread = 4x8
// blocks [GB, GB+HB): histogram over edges
__global__ __launch_bounds__(256) void gemm_hist_kernel(
    const float* __restrict__ x, const float* __restrict__ W,
    const void* __restrict__ ei_raw, int N, long E, int GB)
{
    if ((int)blockIdx.x < GB) {
        __shared__ float Xs[64][D];          // 32 KB
        const int tid = threadIdx.x;
        const int r0b = blockIdx.x * 64;

        for (int i = tid; i < 64 * 32; i += 256) {
            int r = i >> 5, kq = i & 31;
            float4 v = make_float4(0.f, 0.f, 0.f, 0.f);
            if (r0b + r < N) v = *(const float4*)&x[(size_t)(r0b + r) * D + kq * 4];
            *(float4*)&Xs[r][kq * 4] = v;
        }
        __syncthreads();

        const int tx = tid & 15, ty = tid >> 4;
        const int r0 = ty * 4;
        const int c0 = tx * 8;

        float acc[4][8];
        #pragma unroll
        for (int i = 0; i < 4; i++)
            #pragma unroll
            for (int j = 0; j < 8; j++) acc[i][j] = 0.0f;

        #pragma unroll 4
        for (int k = 0; k < D; k++) {
            float4 w0 = __ldg((const float4*)&W[k * D + c0]);
            float4 w1 = __ldg((const float4*)&W[k * D + c0 + 4]);
            float xr[4];
            #pragma unroll
            for (int i = 0; i < 4; i++) xr[i] = Xs[r0 + i][k];
            #pragma unroll
            for (int i = 0; i < 4; i++) {
                acc[i][0] += xr[i] * w0.x; acc[i][1] += xr[i] * w0.y;
                acc[i][2] += xr[i] * w0.z; acc[i][3] += xr[i] * w0.w;
                acc[i][4] += xr[i] * w1.x; acc[i][5] += xr[i] * w1.y;
                acc[i][6] += xr[i] * w1.z; acc[i][7] += xr[i] * w1.w;
            }
        }

        #pragma unroll
        for (int i = 0; i < 4; i++) {
            int r = r0b + r0 + i;
            if (r < N) {
                uint4 pk;
                pk.x = h2_to_u32(__floats2half2_rn(acc[i][0], acc[i][1]));
                pk.y = h2_to_u32(__floats2half2_rn(acc[i][2], acc[i][3]));
                pk.z = h2_to_u32(__floats2half2_rn(acc[i][4], acc[i][5]));
                pk.w = h2_to_u32(__floats2half2_rn(acc[i][6], acc[i][7]));
                *(uint4*)(g_XWh + (size_t)r * D + c0) = pk;
            }
        }
    } else {
        long e = (long)(blockIdx.x - GB) * 256 + threadIdx.x;
        if (e >= E) return;
        int row, col;
        if (g_ei64) {
            const long long* p = (const long long*)ei_raw;
            row = (int)p[e]; col = (int)p[E + e];
        } else {
            const int* p = (const int*)ei_raw;
            row = p[e]; col = p[E + e];
        }
        atomicAdd(&g_deg[row], 1);
        atomicAdd(&g_deg[col], 1);
    }
}

// ---------------- 3-kernel exclusive scan over g_deg ----------------
__global__ __launch_bounds__(1024) void scan1_kernel(int N) {
    __shared__ int sh[1024];
    int t = threadIdx.x;
    int i = blockIdx.x * 1024 + t;
    int v = (i < N) ? g_deg[i] : 0;
    sh[t] = v;
    __syncthreads();
    #pragma unroll
    for (int off = 1; off < 1024; off <<= 1) {
        int add = (t >= off) ? sh[t - off] : 0;
        __syncthreads();
        sh[t] += add;
        __syncthreads();
    }
    if (i < N) g_scan[i] = sh[t];
    if (t == 1023 && blockIdx.x < 128) g_part[blockIdx.x] = sh[1023];
}

__global__ void scan2_kernel(int nb) {
    if (threadIdx.x == 0) {
        if (nb > 128) nb = 128;
        int acc = 0;
        for (int b = 0; b < nb; b++) { int v = g_part[b]; g_part[b] = acc; acc += v; }
    }
}

__global__ __launch_bounds__(1024) void scan3_kernel(int N) {
    int i = blockIdx.x * 1024 + threadIdx.x;
    if (i >= N) return;
    int base = g_part[blockIdx.x];
    int inc = g_scan[i];
    int excl = base + inc - g_deg[i];
    g_off[i] = excl;
    g_cursor[i] = excl;
    if (i == N - 1) g_off[N] = base + inc;
}

// ---------------- fill adjacency ----------------
__global__ __launch_bounds__(256) void fill_kernel(
    const void* __restrict__ ei_raw, const void* __restrict__ et_raw,
    const float* __restrict__ alpha, long E)
{
    long e = (long)blockIdx.x * blockDim.x + threadIdx.x;
    if (e >= E) return;
    int row, col, et;
    if (g_ei64) {
        const long long* p = (const long long*)ei_raw;
        row = (int)p[e]; col = (int)p[E + e];
    } else {
        const int* p = (const int*)ei_raw;
        row = p[e]; col = p[E + e];
    }
    if (g_et64) et = (int)((const long long*)et_raw)[e];
    else        et = ((const int*)et_raw)[e];
    unsigned a = __float_as_uint(__ldg(alpha + et));
    int p1 = atomicAdd(&g_cursor[row], 1);
    g_adj[p1] = make_uint2((unsigned)col, a);
    int p2 = atomicAdd(&g_cursor[col], 1);
    g_adj[p2] = make_uint2((unsigned)row, a);
}

// ---------------- gather (fp16 source): warp per node, fused bias/self/stats ----------------
__device__ __forceinline__ void acc_half4(float4& acc, float a, uint2 u) {
    float2 lo = __half22float2(u32_to_h2(u.x));
    float2 hi = __half22float2(u32_to_h2(u.y));
    acc.x += a * lo.x; acc.y += a * lo.y;
    acc.z += a * hi.x; acc.w += a * hi.y;
}

__global__ __launch_bounds__(256) void gather_kernel(
    const float* __restrict__ alpha, const float* __restrict__ bias,
    float* __restrict__ out, int N, int selfRel)
{
    const int lane = threadIdx.x & 31;
    const int warpG = (blockIdx.x * blockDim.x + threadIdx.x) >> 5;
    const int nWarps = (gridDim.x * blockDim.x) >> 5;
    const uint2* XH = (const uint2*)g_XWh;      // 4 halves per entry, 32 per row
    const uint4* adj4 = (const uint4*)g_adj;

    const float a2 = 2.0f * __ldg(alpha + selfRel);
    const float4 b4 = __ldg((const float4*)bias + lane);

    float s0 = 0, s1 = 0, s2 = 0, s3 = 0;
    float q0 = 0, q1 = 0, q2 = 0, q3 = 0;

    for (int i = warpG; i < N; i += nWarps) {
        int st = g_off[i], en = g_off[i + 1];
        float4 acc = make_float4(b4.x, b4.y, b4.z, b4.w);
        acc_half4(acc, a2, XH[(size_t)i * 32 + lane]);

        int j = st;
        if ((j & 1) && j < en) {
            uint2 e0 = g_adj[j];
            acc_half4(acc, __uint_as_float(e0.y), XH[(size_t)e0.x * 32 + lane]);
            j++;
        }
        for (; j + 4 <= en; j += 4) {
            uint4 p0 = adj4[j >> 1];
            uint4 p1 = adj4[(j >> 1) + 1];
            uint2 v0 = XH[(size_t)p0.x * 32 + lane];
            uint2 v1 = XH[(size_t)p0.z * 32 + lane];
            uint2 v2 = XH[(size_t)p1.x * 32 + lane];
            uint2 v3 = XH[(size_t)p1.z * 32 + lane];
            acc_half4(acc, __uint_as_float(p0.y), v0);
            acc_half4(acc, __uint_as_float(p0.w), v1);
            acc_half4(acc, __uint_as_float(p1.y), v2);
            acc_half4(acc, __uint_as_float(p1.w), v3);
        }
        for (; j < en; j++) {
            uint2 e0 = g_adj[j];
            acc_half4(acc, __uint_as_float(e0.y), XH[(size_t)e0.x * 32 + lane]);
        }

        ((float4*)out)[(size_t)i * 32 + lane] = acc;
        s0 += acc.x; s1 += acc.y; s2 += acc.z; s3 += acc.w;
        q0 += acc.x * acc.x; q1 += acc.y * acc.y;
        q2 += acc.z * acc.z; q3 += acc.w * acc.w;
    }

    // block-level stats reduction
    __shared__ float ssum[D], ssq[D];
    int t = threadIdx.x;
    if (t < D) { ssum[t] = 0.0f; ssq[t] = 0.0f; }
    __syncthreads();
    int c = lane * 4;
    atomicAdd(&ssum[c + 0], s0); atomicAdd(&ssum[c + 1], s1);
    atomicAdd(&ssum[c + 2], s2); atomicAdd(&ssum[c + 3], s3);
    atomicAdd(&ssq[c + 0], q0);  atomicAdd(&ssq[c + 1], q1);
    atomicAdd(&ssq[c + 2], q2);  atomicAdd(&ssq[c + 3], q3);
    __syncthreads();
    if (t < D) {
        int bank = blockIdx.x & (NBANK - 1);
        atomicAdd(&g_sumP[bank][t], ssum[t]);
        atomicAdd(&g_sumsqP[bank][t], ssq[t]);
    }
}

// ---------------- normalize + copy r ----------------
__global__ __launch_bounds__(256) void norm_kernel(
    float* __restrict__ out, const float* __restrict__ gamma,
    const float* __restrict__ beta, const float* __restrict__ r_in,
    float* __restrict__ r_out, int N, long r_count)
{
    __shared__ float sc[D], sh[D];
    const int t = threadIdx.x;
    if (t < D) {
        float s = 0.0f, q = 0.0f;
        #pragma unroll
        for (int b = 0; b < NBANK; b++) { s += g_sumP[b][t]; q += g_sumsqP[b][t]; }
        float invN = 1.0f / (float)N;
        float mean = s * invN;
        float var = q * invN - mean * mean;
        float scl = gamma[t] * rsqrtf(var + BN_EPS);
        sc[t] = scl;
        sh[t] = beta[t] - mean * scl;
    }
    __syncthreads();

    size_t total = (size_t)N * D;
    size_t stride = (size_t)gridDim.x * blockDim.x;
    for (size_t idx = (size_t)blockIdx.x * blockDim.x + t; idx < total; idx += stride) {
        int c = (int)(idx & (D - 1));
        out[idx] = out[idx] * sc[c] + sh[c];
    }
    for (size_t idx = (size_t)blockIdx.x * blockDim.x + t; idx < (size_t)r_count; idx += stride) {
        r_out[idx] = r_in[idx];
    }
}

// ---------------- launch ----------------
extern "C" void kernel_launch(void* const* d_in, const int* in_sizes, int n_in,
                              void* d_out, int out_size)
{
    const float* x     = (const float*)d_in[0];
    const float* r     = (const float*)d_in[1];
    const void*  ei    = d_in[2];
    const void*  etype = d_in[3];
    const float* W     = (const float*)d_in[4];
    const float* alpha = (const float*)d_in[5];
    const float* bias  = (const float*)d_in[6];
    const float* gamma = (const float*)d_in[7];
    const float* beta  = (const float*)d_in[8];
    float* out = (float*)d_out;

    const int  N       = in_sizes[0] / D;       // 100000
    const long E       = (long)in_sizes[3];     // 1600000
    const int  numRel  = in_sizes[1] / D;       // 1001
    const int  selfRel = numRel - 1;            // 1000
    const long r_count = (long)in_sizes[1];

    float* r_out = out + (size_t)N * D;
    const int NB = (N + 1023) / 1024;
    const int GB = (N + 63) / 64;
    const int HB = (int)((E + 255) / 256);

    prologue_kernel<<<(N + 255) / 256, 256>>>((const int*)ei, (const int*)etype, N);

    gemm_hist_kernel<<<GB + HB, 256>>>(x, W, ei, N, E, GB);

    scan1_kernel<<<NB, 1024>>>(N);
    scan2_kernel<<<1, 32>>>(NB);
    scan3_kernel<<<NB, 1024>>>(N);
    fill_kernel<<<HB, 256>>>(ei, etype, alpha, E);

    gather_kernel<<<1024, 256>>>(alpha, bias, out, N, selfRel);

    norm_kernel<<<2048, 256>>>(out, gamma, beta, r, r_out, N, r_count);
}